// round 16
// baseline (speedup 1.0000x reference)
#include <cuda_runtime.h>
#include <cuda_bf16.h>
#include <math.h>
#include <stdint.h>

#define BATCH 4
#define NSEQ 8192
#define NSEQP (NSEQ + 2)
#define DMODEL 1024
#define HID 512
#define MTOT (BATCH * NSEQ)   // 32768
#define FIXCAP 8192
#define FG 4

// ---------------- scratch (device globals; no allocation allowed) ----------------
__device__ float g_w1r[3 * DMODEL * HID];      // conv1 weights [k=t*C+i][o]  (fixup)
__device__ float g_w2r[3 * HID * HID];         // conv2 weights [k][o]        (fixup)
__device__ float g_wi1t[HID * HID];            // imp1 weights transposed [i][o] (fixup)
__device__ __nv_bfloat16 g_w1th[HID * 3 * DMODEL];  // conv1 weights [o][k] K-major bf16
__device__ __nv_bfloat16 g_w2th[HID * 3 * HID];     // conv2 weights [o][k] K-major bf16
__device__ __nv_bfloat16 g_wi1th[HID * HID];        // imp1 weights [o][i] bf16
__device__ __nv_bfloat16 g_xph[BATCH * NSEQP * DMODEL];  // x bf16, zero-padded rows
__device__ __nv_bfloat16 g_h1ph[BATCH * NSEQP * HID];    // h1 bf16, zero-padded rows
__device__ __nv_bfloat16 g_h2h[MTOT * HID];    // conv2 output bf16
__device__ float g_logits_part[4 * MTOT];      // per-N-tile logits partials
__device__ float g_sparse[MTOT * 2];           // G * mask
__device__ float g_mask[MTOT];
__device__ unsigned int g_mask_count;
__device__ unsigned int g_fix_count;
__device__ int g_fix_list[FIXCAP];
__device__ unsigned int g_fix2_count;
__device__ int g_fix_list2[FIXCAP];

struct Cx { float x, y; };
__device__ Cx g_Ls[MTOT];
__device__ Cx g_Rs[MTOT];

// ---------------- helpers ----------------
__device__ __forceinline__ Cx cmul(Cx a, Cx b) { Cx r; r.x = a.x*b.x - a.y*b.y; r.y = a.x*b.y + a.y*b.x; return r; }
__device__ __forceinline__ Cx cadd(Cx a, Cx b) { Cx r; r.x = a.x+b.x; r.y = a.y+b.y; return r; }
__device__ __forceinline__ Cx csub(Cx a, Cx b) { Cx r; r.x = a.x-b.x; r.y = a.y-b.y; return r; }
__device__ __forceinline__ Cx cscale(Cx a, float s) { Cx r; r.x = a.x*s; r.y = a.y*s; return r; }
__device__ __forceinline__ Cx crecip(Cx a) {
    float inv = 1.0f / (a.x*a.x + a.y*a.y);
    Cx r; r.x = a.x*inv; r.y = -a.y*inv; return r;
}
__device__ __forceinline__ Cx cdiv(Cx a, Cx b) { return cmul(a, crecip(b)); }

struct Mat { Cx e00, e01, e10, e11; };
__device__ __forceinline__ Mat mmul(const Mat& A, const Mat& B) {
    Mat C;
    C.e00 = cadd(cmul(A.e00, B.e00), cmul(A.e01, B.e10));
    C.e01 = cadd(cmul(A.e00, B.e01), cmul(A.e01, B.e11));
    C.e10 = cadd(cmul(A.e10, B.e00), cmul(A.e11, B.e10));
    C.e11 = cadd(cmul(A.e10, B.e01), cmul(A.e11, B.e11));
    return C;
}
__device__ __forceinline__ void mnorm(Mat& M) {
    float s = fmaxf(fmaxf(fmaxf(fabsf(M.e00.x), fabsf(M.e00.y)),
                          fmaxf(fabsf(M.e01.x), fabsf(M.e01.y))),
                    fmaxf(fmaxf(fabsf(M.e10.x), fabsf(M.e10.y)),
                          fmaxf(fabsf(M.e11.x), fabsf(M.e11.y))));
    float inv = (s > 0.0f) ? (1.0f / s) : 1.0f;
    M.e00 = cscale(M.e00, inv); M.e01 = cscale(M.e01, inv);
    M.e10 = cscale(M.e10, inv); M.e11 = cscale(M.e11, inv);
}

__device__ __forceinline__ void kadd(float& s, float& c, float v) {
    float y = v - c;
    float t = s + y;
    c = (t - s) - y;
    s = t;
}

__device__ __forceinline__ uint32_t bf2u32(float a, float b) {
    __nv_bfloat162 h = __floats2bfloat162_rn(a, b);
    return *(uint32_t*)&h;
}

__device__ __forceinline__ uint32_t smem_to_u32(const void* smem_ptr) {
    uint32_t addr;
    asm("{ .reg .u64 tmp; cvta.to.shared.u64 tmp, %1; cvt.u32.u64 %0, tmp; }"
        : "=r"(addr) : "l"(smem_ptr));
    return addr;
}

__device__ __forceinline__ void cpasync16(uint32_t dst, const void* src) {
    asm volatile("cp.async.cg.shared.global [%0], [%1], 16;"
                 :: "r"(dst), "l"(__cvta_generic_to_global(src)));
}
#define CP_COMMIT() asm volatile("cp.async.commit_group;" ::: "memory")
#define CP_WAIT0()  asm volatile("cp.async.wait_group 0;" ::: "memory")
#define CP_WAIT1()  asm volatile("cp.async.wait_group 1;" ::: "memory")

__device__ __forceinline__ void apply_decision(int idx, float mk,
                                               const float* v, float* out, int out_size) {
    float old = g_mask[idx];
    if (mk != old) {
        g_mask[idx] = mk;
        if (out_size >= 3 * MTOT + 1) out[2 * MTOT + idx] = mk;
        float d = v[idx] - 2.0f;
        Cx L = g_Ls[idx], R = g_Rs[idx];
        Cx den; den.x = L.x + R.x + d; den.y = L.y + R.y - 1.0f;
        float inv = 1.0f / (den.x * den.x + den.y * den.y);
        g_sparse[idx * 2 + 0] = den.x * inv * mk;
        g_sparse[idx * 2 + 1] = -den.y * inv * mk;
        atomicAdd(&g_mask_count, (mk > old) ? 1u : 0xFFFFFFFFu);
    }
}

// ---------------- prep ----------------
__global__ void prep_kernel(const float* __restrict__ w1,
                            const float* __restrict__ w2,
                            const float* __restrict__ wi1)
{
    int idx = blockIdx.x * blockDim.x + threadIdx.x;
    int stride = gridDim.x * blockDim.x;
    if (idx == 0) { g_mask_count = 0u; g_fix_count = 0u; g_fix2_count = 0u; }
    for (int t = idx; t < HID * DMODEL * 3; t += stride) {
        int o = t / (DMODEL * 3); int r = t - o * (DMODEL * 3);
        int i = r / 3; int k = r - i * 3;
        float w = w1[t];
        g_w1r[(k * DMODEL + i) * HID + o] = w;
        g_w1th[(size_t)o * (3 * DMODEL) + k * DMODEL + i] = __float2bfloat16(w);
    }
    for (int t = idx; t < HID * HID * 3; t += stride) {
        int o = t / (HID * 3); int r = t - o * (HID * 3);
        int i = r / 3; int k = r - i * 3;
        float w = w2[t];
        g_w2r[(k * HID + i) * HID + o] = w;
        g_w2th[(size_t)o * (3 * HID) + k * HID + i] = __float2bfloat16(w);
    }
    for (int t = idx; t < HID * HID; t += stride) {
        int o = t / HID; int i = t - o * HID;
        float w = wi1[t];
        g_wi1t[i * HID + o] = w;
        g_wi1th[t] = __float2bfloat16(w);
    }
}

// ---------------- pad ----------------
__global__ void pad_kernel(const float* __restrict__ x)
{
    const int D8 = DMODEL / 8;
    int idx = blockIdx.x * blockDim.x + threadIdx.x;
    int stride = gridDim.x * blockDim.x;
    const int total = BATCH * NSEQP * D8;
    uint4* __restrict__ xp = (uint4*)g_xph;
    for (int t = idx; t < total; t += stride) {
        int pr = t / D8;
        int c = t - pr * D8;
        int b = pr / NSEQP;
        int r = pr - b * NSEQP;
        uint4 o = make_uint4(0, 0, 0, 0);
        if (r >= 1 && r <= NSEQ) {
            const float4* src = (const float4*)(x + ((size_t)b * NSEQ + (r - 1)) * DMODEL + c * 8);
            float4 a = src[0], bb = src[1];
            o.x = bf2u32(a.x, a.y);  o.y = bf2u32(a.z, a.w);
            o.z = bf2u32(bb.x, bb.y); o.w = bf2u32(bb.z, bb.w);
        }
        xp[t] = o;
    }
    const int H8 = HID / 8;
    uint4* __restrict__ h1p = (uint4*)g_h1ph;
    for (int t = idx; t < 2 * BATCH * H8; t += stride) {
        int which = t / H8;
        int c = t - which * H8;
        int b = which >> 1;
        size_t pr = (size_t)b * NSEQP + ((which & 1) ? (NSEQP - 1) : 0);
        h1p[pr * H8 + c] = make_uint4(0, 0, 0, 0);
    }
}

// ---------------- bf16 mma.sync + ldmatrix + cp.async GEMM (K-chunk 64, 3-stage) ----------------
template<int C, int TAPS, int OUTMODE, bool PADDED_IN>
__global__ __launch_bounds__(256, 2)
void mma_gemm_kernel(const __nv_bfloat16* __restrict__ A,
                     const __nv_bfloat16* __restrict__ Bt,
                     const float* __restrict__ bias,
                     void* __restrict__ OutV,
                     const float* __restrict__ w2)
{
    constexpr int K = TAPS * C;
    constexpr int NC = K / 64;
    constexpr int LDS = 72;
    constexpr uint32_t BUFB = 128 * LDS * 2;

    extern __shared__ char smem[];
    const int tid = threadIdx.x;
    const int wid = tid >> 5, lane = tid & 31;
    const int bid = blockIdx.x;
    const int m0 = (bid >> 2) * 128;
    const int n0 = (bid & 3) * 128;
    const int nt = bid & 3;

    const uint32_t smemB = smem_to_u32(smem);
    uint32_t aBase[3], bBase[3];
#pragma unroll
    for (int s = 0; s < 3; s++) {
        aBase[s] = smemB + s * BUFB;
        bBase[s] = smemB + (3 + s) * BUFB;
    }

    const int srow = tid >> 3;
    const int sseg = tid & 7;
    const __nv_bfloat16* aP[4];
    const __nv_bfloat16* bP[4];
#pragma unroll
    for (int j = 0; j < 4; j++) {
        int row = srow + 32 * j;
        int am = m0 + row;
        size_t aRowIdx = PADDED_IN
            ? ((size_t)(am >> 13) * NSEQP + (size_t)(am & (NSEQ - 1)))
            : (size_t)am;
        aP[j] = A + aRowIdx * C + sseg * 8;
        bP[j] = Bt + (size_t)(n0 + row) * K + sseg * 8;
    }
    const uint32_t stOffBase = (uint32_t)(srow * LDS + sseg * 8) * 2;
    const uint32_t stRowStep = (uint32_t)(32 * LDS * 2);

    const int wm = (wid & 3) * 32;
    const int wn = (wid >> 2) * 64;

    const int r8 = lane & 7, jb = lane >> 3;
    const uint32_t lmOff = (uint32_t)(((jb & 1) * 8 + r8) * (LDS * 2) + (jb >> 1) * 16);

    float acc[2][8][4];
#pragma unroll
    for (int i = 0; i < 2; i++)
#pragma unroll
        for (int j = 0; j < 8; j++)
#pragma unroll
            for (int q = 0; q < 4; q++) acc[i][j][q] = 0.f;

    auto stageAsync = [&](int buf, int c) {
#pragma unroll
        for (int j = 0; j < 4; j++) {
            cpasync16(aBase[buf] + stOffBase + j * stRowStep, aP[j] + c * 64);
            cpasync16(bBase[buf] + stOffBase + j * stRowStep, bP[j] + c * 64);
        }
        CP_COMMIT();
    };

    stageAsync(0, 0);
    stageAsync(1, 1);
    CP_WAIT1();
    __syncthreads();

    for (int c = 0; c < NC; c++) {
        const int buf = c % 3;

#pragma unroll
        for (int ks = 0; ks < 4; ks++) {
            const uint32_t kkB = ks * 32;
            uint32_t af[2][4], bq[4][4];
#pragma unroll
            for (int i = 0; i < 2; i++) {
                uint32_t addr = aBase[buf] + (uint32_t)((wm + i * 16) * (LDS * 2)) + kkB + lmOff;
                asm volatile("ldmatrix.sync.aligned.m8n8.x4.shared.b16 {%0,%1,%2,%3}, [%4];"
                             : "=r"(af[i][0]), "=r"(af[i][1]), "=r"(af[i][2]), "=r"(af[i][3])
                             : "r"(addr));
            }
#pragma unroll
            for (int jj = 0; jj < 4; jj++) {
                uint32_t addr = bBase[buf] + (uint32_t)((wn + jj * 16) * (LDS * 2)) + kkB + lmOff;
                asm volatile("ldmatrix.sync.aligned.m8n8.x4.shared.b16 {%0,%1,%2,%3}, [%4];"
                             : "=r"(bq[jj][0]), "=r"(bq[jj][1]), "=r"(bq[jj][2]), "=r"(bq[jj][3])
                             : "r"(addr));
            }
#pragma unroll
            for (int i = 0; i < 2; i++) {
#pragma unroll
                for (int jj = 0; jj < 4; jj++) {
                    asm volatile(
                        "mma.sync.aligned.m16n8k16.row.col.f32.bf16.bf16.f32 "
                        "{%0,%1,%2,%3}, {%4,%5,%6,%7}, {%8,%9}, {%0,%1,%2,%3};"
                        : "+f"(acc[i][2*jj][0]), "+f"(acc[i][2*jj][1]),
                          "+f"(acc[i][2*jj][2]), "+f"(acc[i][2*jj][3])
                        : "r"(af[i][0]), "r"(af[i][1]), "r"(af[i][2]), "r"(af[i][3]),
                          "r"(bq[jj][0]), "r"(bq[jj][2]));
                    asm volatile(
                        "mma.sync.aligned.m16n8k16.row.col.f32.bf16.bf16.f32 "
                        "{%0,%1,%2,%3}, {%4,%5,%6,%7}, {%8,%9}, {%0,%1,%2,%3};"
                        : "+f"(acc[i][2*jj+1][0]), "+f"(acc[i][2*jj+1][1]),
                          "+f"(acc[i][2*jj+1][2]), "+f"(acc[i][2*jj+1][3])
                        : "r"(af[i][0]), "r"(af[i][1]), "r"(af[i][2]), "r"(af[i][3]),
                          "r"(bq[jj][1]), "r"(bq[jj][3]));
                }
            }
        }

        __syncthreads();
        if (c + 2 < NC) {
            stageAsync((c + 2) % 3, c + 2);
            CP_WAIT1();
            __syncthreads();
        } else if (c + 1 < NC) {
            CP_WAIT0();
            __syncthreads();
        }
    }

    const int g = lane >> 2;
    const int t2 = (lane & 3) * 2;

    if (OUTMODE == 2) {
        __shared__ float red[128][2];
#pragma unroll
        for (int i = 0; i < 2; i++) {
            float p0 = 0.f, p1 = 0.f;
#pragma unroll
            for (int j = 0; j < 8; j++) {
                const int gcol = n0 + wn + j * 8 + t2;
                const float b0 = bias[gcol], b1 = bias[gcol + 1];
                const float w20 = w2[gcol], w21 = w2[gcol + 1];
                p0 = fmaf(fmaxf(acc[i][j][0] + b0, 0.f), w20, p0);
                p0 = fmaf(fmaxf(acc[i][j][1] + b1, 0.f), w21, p0);
                p1 = fmaf(fmaxf(acc[i][j][2] + b0, 0.f), w20, p1);
                p1 = fmaf(fmaxf(acc[i][j][3] + b1, 0.f), w21, p1);
            }
            p0 += __shfl_xor_sync(0xffffffffu, p0, 1);
            p0 += __shfl_xor_sync(0xffffffffu, p0, 2);
            p1 += __shfl_xor_sync(0xffffffffu, p1, 1);
            p1 += __shfl_xor_sync(0xffffffffu, p1, 2);
            if ((lane & 3) == 0) {
                red[wm + i * 16 + g][wid >> 2]     = p0;
                red[wm + i * 16 + 8 + g][wid >> 2] = p1;
            }
        }
        __syncthreads();
        if (tid < 128) {
            float* lp = (float*)OutV;
            lp[nt * MTOT + m0 + tid] = red[tid][0] + red[tid][1];
        }
        return;
    }

#pragma unroll
    for (int i = 0; i < 2; i++) {
        const int mr0 = m0 + wm + i * 16 + g;
        const int mr1 = mr0 + 8;
        size_t or0, or1;
        if (OUTMODE == 0) {
            or0 = (size_t)(mr0 >> 13) * NSEQP + 1 + (size_t)(mr0 & (NSEQ - 1));
            or1 = (size_t)(mr1 >> 13) * NSEQP + 1 + (size_t)(mr1 & (NSEQ - 1));
        } else {
            or0 = (size_t)mr0;
            or1 = (size_t)mr1;
        }
        __nv_bfloat16* O = (__nv_bfloat16*)OutV;
#pragma unroll
        for (int j = 0; j < 8; j++) {
            const int gcol = n0 + wn + j * 8 + t2;
            const float b0 = bias[gcol], b1 = bias[gcol + 1];
            *(uint32_t*)(O + or0 * HID + gcol) =
                bf2u32(fmaxf(acc[i][j][0] + b0, 0.f), fmaxf(acc[i][j][1] + b1, 0.f));
            *(uint32_t*)(O + or1 * HID + gcol) =
                bf2u32(fmaxf(acc[i][j][2] + b0, 0.f), fmaxf(acc[i][j][3] + b1, 0.f));
        }
    }
}
static constexpr int MMA_SMEM = 6 * 128 * 72 * 2;   // 110592 bytes

// ---------------- Green's function ----------------
__global__ __launch_bounds__(256)
void green_kernel(const float* __restrict__ v)
{
    const int b = blockIdx.x >> 1;
    const int dir = blockIdx.x & 1;
    const int t = threadIdx.x;
    constexpr int LOC = NSEQ / 256;
    const float* vb = v + b * NSEQ;

    Mat P;
    P.e00.x = 1.f; P.e00.y = 0.f; P.e01.x = 0.f; P.e01.y = 0.f;
    P.e10.x = 0.f; P.e10.y = 0.f; P.e11.x = 1.f; P.e11.y = 0.f;
    for (int j = 0; j < LOC; j++) {
        int s = t * LOC + j;
        int p = dir ? (NSEQ - 1 - s) : s;
        float d = vb[p] - 2.0f;
        Cx a; a.x = -d; a.y = 1.0f;
        float cs = (s == 0) ? 0.0f : 1.0f;
        Cx n00 = csub(cmul(a, P.e00), cscale(P.e10, cs));
        Cx n01 = csub(cmul(a, P.e01), cscale(P.e11, cs));
        P.e10 = P.e00; P.e11 = P.e01;
        P.e00 = n00;   P.e01 = n01;
        if ((j & 7) == 7) mnorm(P);
    }

    __shared__ Mat sm[256];
    sm[t] = P;
    __syncthreads();
    for (int off = 1; off < 256; off <<= 1) {
        Mat Mp;
        const bool has = (t >= off);
        if (has) Mp = sm[t - off];
        __syncthreads();
        if (has) {
            P = mmul(P, Mp);
            mnorm(P);
            sm[t] = P;
        }
        __syncthreads();
    }

    Cx Lp; Lp.x = 1.0f; Lp.y = 0.0f;
    if (t > 0) {
        Mat E = sm[t - 1];
        Lp = cdiv(cadd(E.e00, E.e01), cadd(E.e10, E.e11));
    }

    Cx* outArr = dir ? g_Rs : g_Ls;
    for (int j = 0; j < LOC; j++) {
        int s = t * LOC + j;
        int p = dir ? (NSEQ - 1 - s) : s;
        float d = vb[p] - 2.0f;
        Cx a; a.x = -d; a.y = 1.0f;
        Cx L;
        if (s == 0) L = a;
        else        L = csub(a, crecip(Lp));
        outArr[b * NSEQ + p] = L;
        Lp = L;
    }
}

// ---------------- mask + G + sparse + borderline detection ----------------
__global__ void mask_kernel(const float* __restrict__ u,
                            const float* __restrict__ v,
                            const float* __restrict__ b_imp2,
                            float* __restrict__ out, int out_size)
{
    int idx = blockIdx.x * blockDim.x + threadIdx.x;
    float logit = g_logits_part[idx] + g_logits_part[MTOT + idx]
                + g_logits_part[2 * MTOT + idx] + g_logits_part[3 * MTOT + idx]
                + b_imp2[0];
    float uu = u[idx];
    float g = -logf(-logf(uu + 1e-10f) + 1e-10f);
    float xx = logit + g;
    float soft = 1.0f / (1.0f + expf(-xx));
    float mk = (soft > 0.5f) ? 1.0f : 0.0f;

    if (fabsf(xx) < 5e-2f) {
        unsigned pos = atomicAdd(&g_fix_count, 1u);
        if (pos < FIXCAP) g_fix_list[pos] = idx;
    }

    float d = v[idx] - 2.0f;
    Cx L = g_Ls[idx], R = g_Rs[idx];
    Cx den; den.x = L.x + R.x + d; den.y = L.y + R.y - 1.0f;
    float inv = 1.0f / (den.x * den.x + den.y * den.y);
    float gr = den.x * inv, gi = -den.y * inv;

    g_sparse[idx * 2 + 0] = gr * mk;
    g_sparse[idx * 2 + 1] = gi * mk;
    g_mask[idx] = mk;
    if (out_size >= 3 * MTOT + 1) out[2 * MTOT + idx] = mk;

    unsigned bal = __ballot_sync(0xffffffffu, mk > 0.5f);
    if ((threadIdx.x & 31) == 0) atomicAdd(&g_mask_count, (unsigned)__popc(bal));
}

// ---------------- Tier-1 fixup: BATCHED fp32 recompute (FG items per block) ----------------
// Streams the weight matrices once per block and applies them to FG samples,
// cutting L2 weight traffic by FG x. Decides |x| > 1e-3; forwards rest to Kahan tier.
static constexpr int FIX_SMEM =
    (FG * DMODEL * 6 + FG * HID * 4 + FG * HID + FG * 256) * 4;   // 143360 B

__global__ __launch_bounds__(256)
void fixup_fast_kernel(const float* __restrict__ x, const float* __restrict__ v,
                       const float* __restrict__ u,
                       const float* __restrict__ b1, const float* __restrict__ b2,
                       const float* __restrict__ bi1, const float* __restrict__ bi2,
                       const float* __restrict__ wi2,
                       float* __restrict__ out, int out_size)
{
    extern __shared__ float fsm[];
    float* sx   = fsm;                           // [FG][DMODEL][6]  x rows n-2..n+2 per col
    float* sh1  = sx + FG * DMODEL * 6;          // [FG][HID][4]    h1 at p=0..2 (+pad)
    float* sh2  = sh1 + FG * HID * 4;            // [FG][HID]
    float* sred = sh2 + FG * HID;                // [FG][256]

    const int tid = threadIdx.x;
    unsigned cnt = g_fix_count;
    int total = (cnt < FIXCAP) ? (int)cnt : FIXCAP;

    for (int base = blockIdx.x * FG; base < total; base += gridDim.x * FG) {
        int idxs[FG];
#pragma unroll
        for (int g = 0; g < FG; g++) {
            int item = base + g;
            idxs[g] = g_fix_list[item < total ? item : total - 1];
        }
        __syncthreads();

        // fill sx: [g][c][r], r = row offset (n-2+r), padded stride 6
#pragma unroll
        for (int g = 0; g < FG; g++) {
            int bb = idxs[g] >> 13, n = idxs[g] & (NSEQ - 1);
            for (int t = tid; t < 5 * DMODEL; t += 256) {
                int r = t >> 10, c = t & (DMODEL - 1);
                int pos = n - 2 + r;
                sx[(g * DMODEL + c) * 6 + r] = ((unsigned)pos < (unsigned)NSEQ)
                    ? x[((size_t)bb * NSEQ + pos) * DMODEL + c] : 0.f;
            }
        }
        __syncthreads();

        // ---- stage 1: h1 at n-1..n+1; weights streamed once per block ----
        {
            float s[FG][2][3];
#pragma unroll
            for (int g = 0; g < FG; g++)
#pragma unroll
                for (int a = 0; a < 2; a++)
#pragma unroll
                    for (int p = 0; p < 3; p++) s[g][a][p] = 0.f;

#pragma unroll 2
            for (int i = 0; i < DMODEL; i++) {
                float wa[3], wb[3];
#pragma unroll
                for (int k = 0; k < 3; k++) {
                    const float* wr = g_w1r + ((size_t)k * DMODEL + i) * HID;
                    wa[k] = wr[tid];
                    wb[k] = wr[tid + 256];
                }
#pragma unroll
                for (int g = 0; g < FG; g++) {
                    const float* xb = &sx[(g * DMODEL + i) * 6];
                    float xr0 = xb[0], xr1 = xb[1], xr2 = xb[2], xr3 = xb[3], xr4 = xb[4];
                    float xr[5] = {xr0, xr1, xr2, xr3, xr4};
#pragma unroll
                    for (int k = 0; k < 3; k++)
#pragma unroll
                        for (int p = 0; p < 3; p++) {
                            s[g][0][p] = fmaf(wa[k], xr[p + k], s[g][0][p]);
                            s[g][1][p] = fmaf(wb[k], xr[p + k], s[g][1][p]);
                        }
                }
            }

#pragma unroll
            for (int g = 0; g < FG; g++) {
                int n = idxs[g] & (NSEQ - 1);
#pragma unroll
                for (int a = 0; a < 2; a++) {
                    int o = tid + a * 256;
                    float bo = b1[o];
#pragma unroll
                    for (int p = 0; p < 3; p++) {
                        int pos = n - 1 + p;
                        float val = ((unsigned)pos < (unsigned)NSEQ)
                                  ? fmaxf(s[g][a][p] + bo, 0.f) : 0.f;
                        sh1[(g * HID + o) * 4 + p] = val;
                    }
                }
            }
        }
        __syncthreads();

        // ---- stage 2: h2 at n ----
        {
            float s[FG][2];
#pragma unroll
            for (int g = 0; g < FG; g++) { s[g][0] = 0.f; s[g][1] = 0.f; }

#pragma unroll 2
            for (int i = 0; i < HID; i++) {
                float wa[3], wb[3];
#pragma unroll
                for (int k = 0; k < 3; k++) {
                    const float* wr = g_w2r + ((size_t)k * HID + i) * HID;
                    wa[k] = wr[tid];
                    wb[k] = wr[tid + 256];
                }
#pragma unroll
                for (int g = 0; g < FG; g++) {
                    float4 hv = *(const float4*)&sh1[(g * HID + i) * 4];
                    float h[3] = {hv.x, hv.y, hv.z};
#pragma unroll
                    for (int k = 0; k < 3; k++) {
                        s[g][0] = fmaf(wa[k], h[k], s[g][0]);
                        s[g][1] = fmaf(wb[k], h[k], s[g][1]);
                    }
                }
            }
#pragma unroll
            for (int g = 0; g < FG; g++) {
                sh2[g * HID + tid]       = fmaxf(s[g][0] + b2[tid], 0.f);
                sh2[g * HID + tid + 256] = fmaxf(s[g][1] + b2[tid + 256], 0.f);
            }
        }
        __syncthreads();

        // ---- stage 3: hh * w_imp2 ----
        {
            float s[FG][2];
#pragma unroll
            for (int g = 0; g < FG; g++) { s[g][0] = 0.f; s[g][1] = 0.f; }

#pragma unroll 2
            for (int i = 0; i < HID; i++) {
                float wa = g_wi1t[(size_t)i * HID + tid];
                float wb = g_wi1t[(size_t)i * HID + tid + 256];
#pragma unroll
                for (int g = 0; g < FG; g++) {
                    float h = sh2[g * HID + i];
                    s[g][0] = fmaf(wa, h, s[g][0]);
                    s[g][1] = fmaf(wb, h, s[g][1]);
                }
            }
            float w20 = wi2[tid], w21 = wi2[tid + 256];
            float bia = bi1[tid], bib = bi1[tid + 256];
#pragma unroll
            for (int g = 0; g < FG; g++) {
                float hh0 = fmaxf(s[g][0] + bia, 0.f);
                float hh1 = fmaxf(s[g][1] + bib, 0.f);
                sred[g * 256 + tid] = hh0 * w20 + hh1 * w21;
            }
        }
        __syncthreads();

        for (int off = 128; off > 0; off >>= 1) {
            if (tid < off) {
#pragma unroll
                for (int g = 0; g < FG; g++)
                    sred[g * 256 + tid] += sred[g * 256 + tid + off];
            }
            __syncthreads();
        }

        if (tid == 0) {
#pragma unroll
            for (int g = 0; g < FG; g++) {
                int item = base + g;
                if (item >= total) break;
                int idx = idxs[g];
                float logit = sred[g * 256] + bi2[0];
                float uu = u[idx];
                float gg = -logf(-logf(uu + 1e-10f) + 1e-10f);
                float xx = logit + gg;
                if (fabsf(xx) < 1e-3f) {
                    unsigned pos = atomicAdd(&g_fix2_count, 1u);
                    if (pos < FIXCAP) g_fix_list2[pos] = idx;
                } else {
                    float soft = 1.0f / (1.0f + expf(-xx));
                    float mk = (soft > 0.5f) ? 1.0f : 0.0f;
                    apply_decision(idx, mk, v, out, out_size);
                }
            }
        }
        __syncthreads();
    }
}

// ---------------- Tier-2 fixup: Kahan, exact ----------------
__global__ __launch_bounds__(256)
void fixup_kahan_kernel(const float* __restrict__ x, const float* __restrict__ v,
                        const float* __restrict__ u,
                        const float* __restrict__ b1, const float* __restrict__ b2,
                        const float* __restrict__ bi1, const float* __restrict__ bi2,
                        const float* __restrict__ wi2,
                        float* __restrict__ out, int out_size)
{
    __shared__ float sx[5][DMODEL];
    __shared__ float sh1[3][HID];
    __shared__ float sh2[HID];
    __shared__ float sred[HID];

    const int tid = threadIdx.x;
    unsigned cnt = g_fix2_count;
    int total = (cnt < FIXCAP) ? (int)cnt : FIXCAP;

    for (int item = blockIdx.x; item < total; item += gridDim.x) {
        int idx = g_fix_list2[item];
        int b = idx >> 13;
        int n = idx & (NSEQ - 1);

        for (int i = tid; i < 5 * DMODEL; i += 256) {
            int r = i >> 10, c = i & (DMODEL - 1);
            int pos = n - 2 + r;
            sx[r][c] = ((unsigned)pos < (unsigned)NSEQ)
                     ? x[((size_t)b * NSEQ + pos) * DMODEL + c] : 0.f;
        }
        __syncthreads();

        {
            float s[2][3], cp[2][3];
#pragma unroll
            for (int a = 0; a < 2; a++)
#pragma unroll
                for (int p = 0; p < 3; p++) { s[a][p] = 0.f; cp[a][p] = 0.f; }
#pragma unroll
            for (int k = 0; k < 3; k++) {
                const float* wrow = g_w1r + (size_t)k * DMODEL * HID;
                for (int i = 0; i < DMODEL; i++) {
                    float wa = wrow[(size_t)i * HID + tid];
                    float wb = wrow[(size_t)i * HID + tid + 256];
                    float x0 = sx[k + 0][i];
                    float x1 = sx[k + 1][i];
                    float x2 = sx[k + 2][i];
                    kadd(s[0][0], cp[0][0], wa * x0);
                    kadd(s[0][1], cp[0][1], wa * x1);
                    kadd(s[0][2], cp[0][2], wa * x2);
                    kadd(s[1][0], cp[1][0], wb * x0);
                    kadd(s[1][1], cp[1][1], wb * x1);
                    kadd(s[1][2], cp[1][2], wb * x2);
                }
            }
#pragma unroll
            for (int a = 0; a < 2; a++) {
                int o = tid + a * 256;
                float bo = b1[o];
#pragma unroll
                for (int p = 0; p < 3; p++) {
                    int pos = n - 1 + p;
                    float val = ((unsigned)pos < (unsigned)NSEQ)
                              ? fmaxf(s[a][p] + cp[a][p] + bo, 0.f) : 0.f;
                    sh1[p][o] = val;
                }
            }
        }
        __syncthreads();

        {
            float s0 = 0.f, c0 = 0.f, s1 = 0.f, c1 = 0.f;
#pragma unroll
            for (int k = 0; k < 3; k++) {
                const float* wrow = g_w2r + (size_t)k * HID * HID;
                for (int i = 0; i < HID; i++) {
                    float hv = sh1[k][i];
                    kadd(s0, c0, wrow[(size_t)i * HID + tid] * hv);
                    kadd(s1, c1, wrow[(size_t)i * HID + tid + 256] * hv);
                }
            }
            sh2[tid]       = fmaxf(s0 + c0 + b2[tid], 0.f);
            sh2[tid + 256] = fmaxf(s1 + c1 + b2[tid + 256], 0.f);
        }
        __syncthreads();

        {
            float s0 = 0.f, c0 = 0.f, s1 = 0.f, c1 = 0.f;
            for (int i = 0; i < HID; i++) {
                float hv = sh2[i];
                kadd(s0, c0, g_wi1t[(size_t)i * HID + tid] * hv);
                kadd(s1, c1, g_wi1t[(size_t)i * HID + tid + 256] * hv);
            }
            float hh0 = fmaxf(s0 + c0 + bi1[tid], 0.f);
            float hh1 = fmaxf(s1 + c1 + bi1[tid + 256], 0.f);
            sred[tid]       = hh0 * wi2[tid];
            sred[tid + 256] = hh1 * wi2[tid + 256];
        }
        __syncthreads();

        if (tid == 0) {
            float s = 0.f, cp = 0.f;
            for (int i = 0; i < HID; i++) kadd(s, cp, sred[i]);
            float logit = s + cp + bi2[0];
            float uu = u[idx];
            float g = -logf(-logf(uu + 1e-10f) + 1e-10f);
            float xx = logit + g;
            float soft = 1.0f / (1.0f + expf(-xx));
            float mk = (soft > 0.5f) ? 1.0f : 0.0f;
            apply_decision(idx, mk, v, out, out_size);
        }
        __syncthreads();
    }
}

// ---------------- tiny interp conv stack + final select ----------------
#define ITILE 128
__global__ __launch_bounds__(256)
void interp_kernel(const float* __restrict__ wi1, const float* __restrict__ bi1,
                   const float* __restrict__ wi2, const float* __restrict__ bi2,
                   const float* __restrict__ wi3, const float* __restrict__ bi3,
                   float* __restrict__ out, int out_size)
{
    __shared__ float sIn[2][ITILE + 12];
    __shared__ float sL1[32][ITILE + 8];
    __shared__ float sL2[32][ITILE + 4];

    const int b = blockIdx.x / (NSEQ / ITILE);
    const int t0 = (blockIdx.x % (NSEQ / ITILE)) * ITILE;
    const int tid = threadIdx.x;

    for (int i = tid; i < 2 * (ITILE + 12); i += 256) {
        int c = i / (ITILE + 12), p = i - c * (ITILE + 12);
        int q = t0 - 6 + p;
        float val = 0.f;
        if ((unsigned)q < (unsigned)NSEQ) val = g_sparse[((size_t)b * NSEQ + q) * 2 + c];
        sIn[c][p] = val;
    }
    __syncthreads();

    for (int i = tid; i < 32 * (ITILE + 8); i += 256) {
        int co = i / (ITILE + 8), p = i - co * (ITILE + 8);
        int apos = t0 - 4 + p;
        float val = 0.f;
        if ((unsigned)apos < (unsigned)NSEQ) {
            float s = bi1[co];
#pragma unroll
            for (int ci = 0; ci < 2; ci++)
#pragma unroll
                for (int k = 0; k < 5; k++)
                    s = fmaf(wi1[co * 10 + ci * 5 + k], sIn[ci][p + k], s);
            val = fmaxf(s, 0.f);
        }
        sL1[co][p] = val;
    }
    __syncthreads();

    for (int i = tid; i < 32 * (ITILE + 4); i += 256) {
        int co = i / (ITILE + 4), p = i - co * (ITILE + 4);
        int apos = t0 - 2 + p;
        float val = 0.f;
        if ((unsigned)apos < (unsigned)NSEQ) {
            float s = bi2[co];
            for (int ci = 0; ci < 32; ci++)
#pragma unroll
                for (int k = 0; k < 5; k++)
                    s = fmaf(wi2[co * 160 + ci * 5 + k], sL1[ci][p + k], s);
            val = fmaxf(s, 0.f);
        }
        sL2[co][p] = val;
    }
    __syncthreads();

    {
        int co = tid & 1, p = tid >> 1;
        float s = bi3[co];
        for (int ci = 0; ci < 32; ci++)
#pragma unroll
            for (int k = 0; k < 5; k++)
                s = fmaf(wi3[co * 160 + ci * 5 + k], sL2[ci][p + k], s);
        int gidx = b * NSEQ + t0 + p;
        float mk = g_mask[gidx];
        float sp = g_sparse[(size_t)gidx * 2 + co];
        out[(size_t)gidx * 2 + co] = (mk > 0.5f) ? sp : s;
    }

    if (blockIdx.x == 0 && tid == 0 && out_size >= 3 * MTOT + 1)
        out[3 * MTOT] = 1.0f - (float)g_mask_count / (float)MTOT;
}

// ---------------- launch ----------------
static void* symaddr(const void* sym) {
    void* p = nullptr;
    cudaGetSymbolAddress(&p, sym);
    return p;
}

extern "C" void kernel_launch(void* const* d_in, const int* in_sizes, int n_in,
                              void* d_out, int out_size)
{
    const float* x      = (const float*)d_in[0];
    const float* v      = (const float*)d_in[1];
    const float* u      = (const float*)d_in[2];
    const float* w_ctx1 = (const float*)d_in[3];
    const float* b_ctx1 = (const float*)d_in[4];
    const float* w_ctx2 = (const float*)d_in[5];
    const float* b_ctx2 = (const float*)d_in[6];
    const float* w_imp1 = (const float*)d_in[7];
    const float* b_imp1 = (const float*)d_in[8];
    const float* w_imp2 = (const float*)d_in[9];
    const float* b_imp2 = (const float*)d_in[10];
    const float* w_int1 = (const float*)d_in[11];
    const float* b_int1 = (const float*)d_in[12];
    const float* w_int2 = (const float*)d_in[13];
    const float* b_int2 = (const float*)d_in[14];
    const float* w_int3 = (const float*)d_in[15];
    const float* b_int3 = (const float*)d_in[16];
    float* out = (float*)d_out;

    __nv_bfloat16* w1th  = (__nv_bfloat16*)symaddr(g_w1th);
    __nv_bfloat16* w2th  = (__nv_bfloat16*)symaddr(g_w2th);
    __nv_bfloat16* wi1th = (__nv_bfloat16*)symaddr(g_wi1th);
    __nv_bfloat16* xph   = (__nv_bfloat16*)symaddr(g_xph);
    __nv_bfloat16* h1ph  = (__nv_bfloat16*)symaddr(g_h1ph);
    __nv_bfloat16* h2h   = (__nv_bfloat16*)symaddr(g_h2h);
    float* lpart = (float*)symaddr(g_logits_part);

    static bool attr_set = false;
    if (!attr_set) {
        cudaFuncSetAttribute(mma_gemm_kernel<DMODEL, 3, 0, true>,
                             cudaFuncAttributeMaxDynamicSharedMemorySize, MMA_SMEM);
        cudaFuncSetAttribute(mma_gemm_kernel<HID, 3, 1, true>,
                             cudaFuncAttributeMaxDynamicSharedMemorySize, MMA_SMEM);
        cudaFuncSetAttribute(mma_gemm_kernel<HID, 1, 2, false>,
                             cudaFuncAttributeMaxDynamicSharedMemorySize, MMA_SMEM);
        cudaFuncSetAttribute(fixup_fast_kernel,
                             cudaFuncAttributeMaxDynamicSharedMemorySize, FIX_SMEM);
        attr_set = true;
    }

    prep_kernel<<<128, 256>>>(w_ctx1, w_ctx2, w_imp1);
    pad_kernel<<<2048, 256>>>(x);

    const int gemmGrid = (MTOT / 128) * 4;
    mma_gemm_kernel<DMODEL, 3, 0, true><<<gemmGrid, 256, MMA_SMEM>>>(xph, w1th, b_ctx1, h1ph, nullptr);
    mma_gemm_kernel<HID, 3, 1, true><<<gemmGrid, 256, MMA_SMEM>>>(h1ph, w2th, b_ctx2, h2h, nullptr);
    mma_gemm_kernel<HID, 1, 2, false><<<gemmGrid, 256, MMA_SMEM>>>(h2h, wi1th, b_imp1, lpart, w_imp2);

    green_kernel<<<8, 256>>>(v);
    mask_kernel<<<MTOT / 256, 256>>>(u, v, b_imp2, out, out_size);
    fixup_fast_kernel<<<160, 256, FIX_SMEM>>>(x, v, u, b_ctx1, b_ctx2, b_imp1, b_imp2, w_imp2, out, out_size);
    fixup_kahan_kernel<<<64, 256>>>(x, v, u, b_ctx1, b_ctx2, b_imp1, b_imp2, w_imp2, out, out_size);
    interp_kernel<<<BATCH * (NSEQ / ITILE), 256>>>(w_int1, b_int1, w_int2, b_int2,
                                                   w_int3, b_int3, out, out_size);
}

// round 17
// speedup vs baseline: 1.5322x; 1.5322x over previous
#include <cuda_runtime.h>
#include <cuda_bf16.h>
#include <math.h>
#include <stdint.h>

#define BATCH 4
#define NSEQ 8192
#define NSEQP (NSEQ + 2)
#define DMODEL 1024
#define HID 512
#define MTOT (BATCH * NSEQ)   // 32768
#define FIXCAP 8192

// ---------------- scratch (device globals; no allocation allowed) ----------------
__device__ float g_w1r[3 * DMODEL * HID];      // conv1 weights [k=t*C+i][o]  (fixup)
__device__ float g_w2r[3 * HID * HID];         // conv2 weights [k][o]        (fixup)
__device__ float g_wi1t[HID * HID];            // imp1 weights transposed [i][o] (fixup)
__device__ __nv_bfloat16 g_w1th[HID * 3 * DMODEL];  // conv1 weights [o][k] K-major bf16
__device__ __nv_bfloat16 g_w2th[HID * 3 * HID];     // conv2 weights [o][k] K-major bf16
__device__ __nv_bfloat16 g_wi1th[HID * HID];        // imp1 weights [o][i] bf16
__device__ __nv_bfloat16 g_xph[BATCH * NSEQP * DMODEL];  // x bf16, zero-padded rows
__device__ __nv_bfloat16 g_h1ph[BATCH * NSEQP * HID];    // h1 bf16, zero-padded rows
__device__ __nv_bfloat16 g_h2h[MTOT * HID];    // conv2 output bf16
__device__ float g_logits_part[4 * MTOT];      // per-N-tile logits partials
__device__ float g_sparse[MTOT * 2];           // G * mask
__device__ float g_mask[MTOT];
__device__ unsigned int g_mask_count;
__device__ unsigned int g_fix_count;
__device__ int g_fix_list[FIXCAP];
__device__ unsigned int g_fix2_count;
__device__ int g_fix_list2[FIXCAP];

struct Cx { float x, y; };
__device__ Cx g_Ls[MTOT];
__device__ Cx g_Rs[MTOT];

// ---------------- helpers ----------------
__device__ __forceinline__ Cx cmul(Cx a, Cx b) { Cx r; r.x = a.x*b.x - a.y*b.y; r.y = a.x*b.y + a.y*b.x; return r; }
__device__ __forceinline__ Cx cadd(Cx a, Cx b) { Cx r; r.x = a.x+b.x; r.y = a.y+b.y; return r; }
__device__ __forceinline__ Cx csub(Cx a, Cx b) { Cx r; r.x = a.x-b.x; r.y = a.y-b.y; return r; }
__device__ __forceinline__ Cx cscale(Cx a, float s) { Cx r; r.x = a.x*s; r.y = a.y*s; return r; }
__device__ __forceinline__ Cx crecip(Cx a) {
    float inv = 1.0f / (a.x*a.x + a.y*a.y);
    Cx r; r.x = a.x*inv; r.y = -a.y*inv; return r;
}
__device__ __forceinline__ Cx cdiv(Cx a, Cx b) { return cmul(a, crecip(b)); }

struct Mat { Cx e00, e01, e10, e11; };
__device__ __forceinline__ Mat mmul(const Mat& A, const Mat& B) {
    Mat C;
    C.e00 = cadd(cmul(A.e00, B.e00), cmul(A.e01, B.e10));
    C.e01 = cadd(cmul(A.e00, B.e01), cmul(A.e01, B.e11));
    C.e10 = cadd(cmul(A.e10, B.e00), cmul(A.e11, B.e10));
    C.e11 = cadd(cmul(A.e10, B.e01), cmul(A.e11, B.e11));
    return C;
}
__device__ __forceinline__ void mnorm(Mat& M) {
    float s = fmaxf(fmaxf(fmaxf(fabsf(M.e00.x), fabsf(M.e00.y)),
                          fmaxf(fabsf(M.e01.x), fabsf(M.e01.y))),
                    fmaxf(fmaxf(fabsf(M.e10.x), fabsf(M.e10.y)),
                          fmaxf(fabsf(M.e11.x), fabsf(M.e11.y))));
    float inv = (s > 0.0f) ? (1.0f / s) : 1.0f;
    M.e00 = cscale(M.e00, inv); M.e01 = cscale(M.e01, inv);
    M.e10 = cscale(M.e10, inv); M.e11 = cscale(M.e11, inv);
}

__device__ __forceinline__ void kadd(float& s, float& c, float v) {
    float y = v - c;
    float t = s + y;
    c = (t - s) - y;
    s = t;
}

__device__ __forceinline__ uint32_t bf2u32(float a, float b) {
    __nv_bfloat162 h = __floats2bfloat162_rn(a, b);
    return *(uint32_t*)&h;
}

__device__ __forceinline__ uint32_t smem_to_u32(const void* smem_ptr) {
    uint32_t addr;
    asm("{ .reg .u64 tmp; cvta.to.shared.u64 tmp, %1; cvt.u32.u64 %0, tmp; }"
        : "=r"(addr) : "l"(smem_ptr));
    return addr;
}

__device__ __forceinline__ void cpasync16(uint32_t dst, const void* src) {
    asm volatile("cp.async.cg.shared.global [%0], [%1], 16;"
                 :: "r"(dst), "l"(__cvta_generic_to_global(src)));
}
#define CP_COMMIT() asm volatile("cp.async.commit_group;" ::: "memory")
#define CP_WAIT0()  asm volatile("cp.async.wait_group 0;" ::: "memory")
#define CP_WAIT1()  asm volatile("cp.async.wait_group 1;" ::: "memory")

__device__ __forceinline__ void apply_decision(int idx, float mk,
                                               const float* v, float* out, int out_size) {
    float old = g_mask[idx];
    if (mk != old) {
        g_mask[idx] = mk;
        if (out_size >= 3 * MTOT + 1) out[2 * MTOT + idx] = mk;
        float d = v[idx] - 2.0f;
        Cx L = g_Ls[idx], R = g_Rs[idx];
        Cx den; den.x = L.x + R.x + d; den.y = L.y + R.y - 1.0f;
        float inv = 1.0f / (den.x * den.x + den.y * den.y);
        g_sparse[idx * 2 + 0] = den.x * inv * mk;
        g_sparse[idx * 2 + 1] = -den.y * inv * mk;
        atomicAdd(&g_mask_count, (mk > old) ? 1u : 0xFFFFFFFFu);
    }
}

// ---------------- prep ----------------
__global__ void prep_kernel(const float* __restrict__ w1,
                            const float* __restrict__ w2,
                            const float* __restrict__ wi1)
{
    int idx = blockIdx.x * blockDim.x + threadIdx.x;
    int stride = gridDim.x * blockDim.x;
    if (idx == 0) { g_mask_count = 0u; g_fix_count = 0u; g_fix2_count = 0u; }
    for (int t = idx; t < HID * DMODEL * 3; t += stride) {
        int o = t / (DMODEL * 3); int r = t - o * (DMODEL * 3);
        int i = r / 3; int k = r - i * 3;
        float w = w1[t];
        g_w1r[(k * DMODEL + i) * HID + o] = w;
        g_w1th[(size_t)o * (3 * DMODEL) + k * DMODEL + i] = __float2bfloat16(w);
    }
    for (int t = idx; t < HID * HID * 3; t += stride) {
        int o = t / (HID * 3); int r = t - o * (HID * 3);
        int i = r / 3; int k = r - i * 3;
        float w = w2[t];
        g_w2r[(k * HID + i) * HID + o] = w;
        g_w2th[(size_t)o * (3 * HID) + k * HID + i] = __float2bfloat16(w);
    }
    for (int t = idx; t < HID * HID; t += stride) {
        int o = t / HID; int i = t - o * HID;
        float w = wi1[t];
        g_wi1t[i * HID + o] = w;
        g_wi1th[t] = __float2bfloat16(w);
    }
}

// ---------------- pad ----------------
__global__ void pad_kernel(const float* __restrict__ x)
{
    const int D8 = DMODEL / 8;
    int idx = blockIdx.x * blockDim.x + threadIdx.x;
    int stride = gridDim.x * blockDim.x;
    const int total = BATCH * NSEQP * D8;
    uint4* __restrict__ xp = (uint4*)g_xph;
    for (int t = idx; t < total; t += stride) {
        int pr = t / D8;
        int c = t - pr * D8;
        int b = pr / NSEQP;
        int r = pr - b * NSEQP;
        uint4 o = make_uint4(0, 0, 0, 0);
        if (r >= 1 && r <= NSEQ) {
            const float4* src = (const float4*)(x + ((size_t)b * NSEQ + (r - 1)) * DMODEL + c * 8);
            float4 a = src[0], bb = src[1];
            o.x = bf2u32(a.x, a.y);  o.y = bf2u32(a.z, a.w);
            o.z = bf2u32(bb.x, bb.y); o.w = bf2u32(bb.z, bb.w);
        }
        xp[t] = o;
    }
    const int H8 = HID / 8;
    uint4* __restrict__ h1p = (uint4*)g_h1ph;
    for (int t = idx; t < 2 * BATCH * H8; t += stride) {
        int which = t / H8;
        int c = t - which * H8;
        int b = which >> 1;
        size_t pr = (size_t)b * NSEQP + ((which & 1) ? (NSEQP - 1) : 0);
        h1p[pr * H8 + c] = make_uint4(0, 0, 0, 0);
    }
}

// ---------------- bf16 mma.sync + ldmatrix + cp.async GEMM (K-chunk 64, 3-stage) ----------------
template<int C, int TAPS, int OUTMODE, bool PADDED_IN>
__global__ __launch_bounds__(256, 2)
void mma_gemm_kernel(const __nv_bfloat16* __restrict__ A,
                     const __nv_bfloat16* __restrict__ Bt,
                     const float* __restrict__ bias,
                     void* __restrict__ OutV,
                     const float* __restrict__ w2)
{
    constexpr int K = TAPS * C;
    constexpr int NC = K / 64;
    constexpr int LDS = 72;
    constexpr uint32_t BUFB = 128 * LDS * 2;

    extern __shared__ char smem[];
    const int tid = threadIdx.x;
    const int wid = tid >> 5, lane = tid & 31;
    const int bid = blockIdx.x;
    const int m0 = (bid >> 2) * 128;
    const int n0 = (bid & 3) * 128;
    const int nt = bid & 3;

    const uint32_t smemB = smem_to_u32(smem);
    uint32_t aBase[3], bBase[3];
#pragma unroll
    for (int s = 0; s < 3; s++) {
        aBase[s] = smemB + s * BUFB;
        bBase[s] = smemB + (3 + s) * BUFB;
    }

    const int srow = tid >> 3;
    const int sseg = tid & 7;
    const __nv_bfloat16* aP[4];
    const __nv_bfloat16* bP[4];
#pragma unroll
    for (int j = 0; j < 4; j++) {
        int row = srow + 32 * j;
        int am = m0 + row;
        size_t aRowIdx = PADDED_IN
            ? ((size_t)(am >> 13) * NSEQP + (size_t)(am & (NSEQ - 1)))
            : (size_t)am;
        aP[j] = A + aRowIdx * C + sseg * 8;
        bP[j] = Bt + (size_t)(n0 + row) * K + sseg * 8;
    }
    const uint32_t stOffBase = (uint32_t)(srow * LDS + sseg * 8) * 2;
    const uint32_t stRowStep = (uint32_t)(32 * LDS * 2);

    const int wm = (wid & 3) * 32;
    const int wn = (wid >> 2) * 64;

    const int r8 = lane & 7, jb = lane >> 3;
    const uint32_t lmOff = (uint32_t)(((jb & 1) * 8 + r8) * (LDS * 2) + (jb >> 1) * 16);

    float acc[2][8][4];
#pragma unroll
    for (int i = 0; i < 2; i++)
#pragma unroll
        for (int j = 0; j < 8; j++)
#pragma unroll
            for (int q = 0; q < 4; q++) acc[i][j][q] = 0.f;

    auto stageAsync = [&](int buf, int c) {
#pragma unroll
        for (int j = 0; j < 4; j++) {
            cpasync16(aBase[buf] + stOffBase + j * stRowStep, aP[j] + c * 64);
            cpasync16(bBase[buf] + stOffBase + j * stRowStep, bP[j] + c * 64);
        }
        CP_COMMIT();
    };

    stageAsync(0, 0);
    stageAsync(1, 1);
    CP_WAIT1();
    __syncthreads();

    for (int c = 0; c < NC; c++) {
        const int buf = c % 3;

#pragma unroll
        for (int ks = 0; ks < 4; ks++) {
            const uint32_t kkB = ks * 32;
            uint32_t af[2][4], bq[4][4];
#pragma unroll
            for (int i = 0; i < 2; i++) {
                uint32_t addr = aBase[buf] + (uint32_t)((wm + i * 16) * (LDS * 2)) + kkB + lmOff;
                asm volatile("ldmatrix.sync.aligned.m8n8.x4.shared.b16 {%0,%1,%2,%3}, [%4];"
                             : "=r"(af[i][0]), "=r"(af[i][1]), "=r"(af[i][2]), "=r"(af[i][3])
                             : "r"(addr));
            }
#pragma unroll
            for (int jj = 0; jj < 4; jj++) {
                uint32_t addr = bBase[buf] + (uint32_t)((wn + jj * 16) * (LDS * 2)) + kkB + lmOff;
                asm volatile("ldmatrix.sync.aligned.m8n8.x4.shared.b16 {%0,%1,%2,%3}, [%4];"
                             : "=r"(bq[jj][0]), "=r"(bq[jj][1]), "=r"(bq[jj][2]), "=r"(bq[jj][3])
                             : "r"(addr));
            }
#pragma unroll
            for (int i = 0; i < 2; i++) {
#pragma unroll
                for (int jj = 0; jj < 4; jj++) {
                    asm volatile(
                        "mma.sync.aligned.m16n8k16.row.col.f32.bf16.bf16.f32 "
                        "{%0,%1,%2,%3}, {%4,%5,%6,%7}, {%8,%9}, {%0,%1,%2,%3};"
                        : "+f"(acc[i][2*jj][0]), "+f"(acc[i][2*jj][1]),
                          "+f"(acc[i][2*jj][2]), "+f"(acc[i][2*jj][3])
                        : "r"(af[i][0]), "r"(af[i][1]), "r"(af[i][2]), "r"(af[i][3]),
                          "r"(bq[jj][0]), "r"(bq[jj][2]));
                    asm volatile(
                        "mma.sync.aligned.m16n8k16.row.col.f32.bf16.bf16.f32 "
                        "{%0,%1,%2,%3}, {%4,%5,%6,%7}, {%8,%9}, {%0,%1,%2,%3};"
                        : "+f"(acc[i][2*jj+1][0]), "+f"(acc[i][2*jj+1][1]),
                          "+f"(acc[i][2*jj+1][2]), "+f"(acc[i][2*jj+1][3])
                        : "r"(af[i][0]), "r"(af[i][1]), "r"(af[i][2]), "r"(af[i][3]),
                          "r"(bq[jj][1]), "r"(bq[jj][3]));
                }
            }
        }

        __syncthreads();
        if (c + 2 < NC) {
            stageAsync((c + 2) % 3, c + 2);
            CP_WAIT1();
            __syncthreads();
        } else if (c + 1 < NC) {
            CP_WAIT0();
            __syncthreads();
        }
    }

    const int g = lane >> 2;
    const int t2 = (lane & 3) * 2;

    if (OUTMODE == 2) {
        __shared__ float red[128][2];
#pragma unroll
        for (int i = 0; i < 2; i++) {
            float p0 = 0.f, p1 = 0.f;
#pragma unroll
            for (int j = 0; j < 8; j++) {
                const int gcol = n0 + wn + j * 8 + t2;
                const float b0 = bias[gcol], b1 = bias[gcol + 1];
                const float w20 = w2[gcol], w21 = w2[gcol + 1];
                p0 = fmaf(fmaxf(acc[i][j][0] + b0, 0.f), w20, p0);
                p0 = fmaf(fmaxf(acc[i][j][1] + b1, 0.f), w21, p0);
                p1 = fmaf(fmaxf(acc[i][j][2] + b0, 0.f), w20, p1);
                p1 = fmaf(fmaxf(acc[i][j][3] + b1, 0.f), w21, p1);
            }
            p0 += __shfl_xor_sync(0xffffffffu, p0, 1);
            p0 += __shfl_xor_sync(0xffffffffu, p0, 2);
            p1 += __shfl_xor_sync(0xffffffffu, p1, 1);
            p1 += __shfl_xor_sync(0xffffffffu, p1, 2);
            if ((lane & 3) == 0) {
                red[wm + i * 16 + g][wid >> 2]     = p0;
                red[wm + i * 16 + 8 + g][wid >> 2] = p1;
            }
        }
        __syncthreads();
        if (tid < 128) {
            float* lp = (float*)OutV;
            lp[nt * MTOT + m0 + tid] = red[tid][0] + red[tid][1];
        }
        return;
    }

#pragma unroll
    for (int i = 0; i < 2; i++) {
        const int mr0 = m0 + wm + i * 16 + g;
        const int mr1 = mr0 + 8;
        size_t or0, or1;
        if (OUTMODE == 0) {
            or0 = (size_t)(mr0 >> 13) * NSEQP + 1 + (size_t)(mr0 & (NSEQ - 1));
            or1 = (size_t)(mr1 >> 13) * NSEQP + 1 + (size_t)(mr1 & (NSEQ - 1));
        } else {
            or0 = (size_t)mr0;
            or1 = (size_t)mr1;
        }
        __nv_bfloat16* O = (__nv_bfloat16*)OutV;
#pragma unroll
        for (int j = 0; j < 8; j++) {
            const int gcol = n0 + wn + j * 8 + t2;
            const float b0 = bias[gcol], b1 = bias[gcol + 1];
            *(uint32_t*)(O + or0 * HID + gcol) =
                bf2u32(fmaxf(acc[i][j][0] + b0, 0.f), fmaxf(acc[i][j][1] + b1, 0.f));
            *(uint32_t*)(O + or1 * HID + gcol) =
                bf2u32(fmaxf(acc[i][j][2] + b0, 0.f), fmaxf(acc[i][j][3] + b1, 0.f));
        }
    }
}
static constexpr int MMA_SMEM = 6 * 128 * 72 * 2;   // 110592 bytes

// ---------------- Green's function ----------------
__global__ __launch_bounds__(256)
void green_kernel(const float* __restrict__ v)
{
    const int b = blockIdx.x >> 1;
    const int dir = blockIdx.x & 1;
    const int t = threadIdx.x;
    constexpr int LOC = NSEQ / 256;
    const float* vb = v + b * NSEQ;

    Mat P;
    P.e00.x = 1.f; P.e00.y = 0.f; P.e01.x = 0.f; P.e01.y = 0.f;
    P.e10.x = 0.f; P.e10.y = 0.f; P.e11.x = 1.f; P.e11.y = 0.f;
    for (int j = 0; j < LOC; j++) {
        int s = t * LOC + j;
        int p = dir ? (NSEQ - 1 - s) : s;
        float d = vb[p] - 2.0f;
        Cx a; a.x = -d; a.y = 1.0f;
        float cs = (s == 0) ? 0.0f : 1.0f;
        Cx n00 = csub(cmul(a, P.e00), cscale(P.e10, cs));
        Cx n01 = csub(cmul(a, P.e01), cscale(P.e11, cs));
        P.e10 = P.e00; P.e11 = P.e01;
        P.e00 = n00;   P.e01 = n01;
        if ((j & 7) == 7) mnorm(P);
    }

    __shared__ Mat sm[256];
    sm[t] = P;
    __syncthreads();
    for (int off = 1; off < 256; off <<= 1) {
        Mat Mp;
        const bool has = (t >= off);
        if (has) Mp = sm[t - off];
        __syncthreads();
        if (has) {
            P = mmul(P, Mp);
            mnorm(P);
            sm[t] = P;
        }
        __syncthreads();
    }

    Cx Lp; Lp.x = 1.0f; Lp.y = 0.0f;
    if (t > 0) {
        Mat E = sm[t - 1];
        Lp = cdiv(cadd(E.e00, E.e01), cadd(E.e10, E.e11));
    }

    Cx* outArr = dir ? g_Rs : g_Ls;
    for (int j = 0; j < LOC; j++) {
        int s = t * LOC + j;
        int p = dir ? (NSEQ - 1 - s) : s;
        float d = vb[p] - 2.0f;
        Cx a; a.x = -d; a.y = 1.0f;
        Cx L;
        if (s == 0) L = a;
        else        L = csub(a, crecip(Lp));
        outArr[b * NSEQ + p] = L;
        Lp = L;
    }
}

// ---------------- mask + G + sparse + borderline detection ----------------
__global__ void mask_kernel(const float* __restrict__ u,
                            const float* __restrict__ v,
                            const float* __restrict__ b_imp2,
                            float* __restrict__ out, int out_size)
{
    int idx = blockIdx.x * blockDim.x + threadIdx.x;
    float logit = g_logits_part[idx] + g_logits_part[MTOT + idx]
                + g_logits_part[2 * MTOT + idx] + g_logits_part[3 * MTOT + idx]
                + b_imp2[0];
    float uu = u[idx];
    float g = -logf(-logf(uu + 1e-10f) + 1e-10f);
    float xx = logit + g;
    float soft = 1.0f / (1.0f + expf(-xx));
    float mk = (soft > 0.5f) ? 1.0f : 0.0f;

    // bf16 path: logit error sigma ~4e-3; 2.5e-2 = ~6 sigma
    if (fabsf(xx) < 2.5e-2f) {
        unsigned pos = atomicAdd(&g_fix_count, 1u);
        if (pos < FIXCAP) g_fix_list[pos] = idx;
    }

    float d = v[idx] - 2.0f;
    Cx L = g_Ls[idx], R = g_Rs[idx];
    Cx den; den.x = L.x + R.x + d; den.y = L.y + R.y - 1.0f;
    float inv = 1.0f / (den.x * den.x + den.y * den.y);
    float gr = den.x * inv, gi = -den.y * inv;

    g_sparse[idx * 2 + 0] = gr * mk;
    g_sparse[idx * 2 + 1] = gi * mk;
    g_mask[idx] = mk;
    if (out_size >= 3 * MTOT + 1) out[2 * MTOT + idx] = mk;

    unsigned bal = __ballot_sync(0xffffffffu, mk > 0.5f);
    if ((threadIdx.x & 31) == 0) atomicAdd(&g_mask_count, (unsigned)__popc(bal));
}

// ---------------- Tier-1 fixup: plain fp32, interleaved partials (R15 version) ----------------
__global__ __launch_bounds__(256)
void fixup_fast_kernel(const float* __restrict__ x, const float* __restrict__ v,
                       const float* __restrict__ u,
                       const float* __restrict__ b1, const float* __restrict__ b2,
                       const float* __restrict__ bi1, const float* __restrict__ bi2,
                       const float* __restrict__ wi2,
                       float* __restrict__ out, int out_size)
{
    __shared__ float sx[5][DMODEL];
    __shared__ float sh1[3][HID];
    __shared__ float sh2[HID];
    __shared__ float sred[HID];

    const int tid = threadIdx.x;
    unsigned cnt = g_fix_count;
    int total = (cnt < FIXCAP) ? (int)cnt : FIXCAP;

    for (int item = blockIdx.x; item < total; item += gridDim.x) {
        int idx = g_fix_list[item];
        int b = idx >> 13;
        int n = idx & (NSEQ - 1);

        for (int i = tid; i < 5 * DMODEL; i += 256) {
            int r = i >> 10, c = i & (DMODEL - 1);
            int pos = n - 2 + r;
            sx[r][c] = ((unsigned)pos < (unsigned)NSEQ)
                     ? x[((size_t)b * NSEQ + pos) * DMODEL + c] : 0.f;
        }
        __syncthreads();

        {
            float s[2][3][2];
#pragma unroll
            for (int a = 0; a < 2; a++)
#pragma unroll
                for (int p = 0; p < 3; p++) { s[a][p][0] = 0.f; s[a][p][1] = 0.f; }
#pragma unroll
            for (int k = 0; k < 3; k++) {
                const float* wrow = g_w1r + (size_t)k * DMODEL * HID;
                for (int i = 0; i < DMODEL; i += 2) {
                    float wa0 = wrow[(size_t)i * HID + tid];
                    float wb0 = wrow[(size_t)i * HID + tid + 256];
                    float wa1 = wrow[(size_t)(i + 1) * HID + tid];
                    float wb1 = wrow[(size_t)(i + 1) * HID + tid + 256];
#pragma unroll
                    for (int p = 0; p < 3; p++) {
                        float x0 = sx[k + p][i];
                        float x1 = sx[k + p][i + 1];
                        s[0][p][0] = fmaf(wa0, x0, s[0][p][0]);
                        s[0][p][1] = fmaf(wa1, x1, s[0][p][1]);
                        s[1][p][0] = fmaf(wb0, x0, s[1][p][0]);
                        s[1][p][1] = fmaf(wb1, x1, s[1][p][1]);
                    }
                }
            }
#pragma unroll
            for (int a = 0; a < 2; a++) {
                int o = tid + a * 256;
                float bo = b1[o];
#pragma unroll
                for (int p = 0; p < 3; p++) {
                    int pos = n - 1 + p;
                    float val = ((unsigned)pos < (unsigned)NSEQ)
                              ? fmaxf(s[a][p][0] + s[a][p][1] + bo, 0.f) : 0.f;
                    sh1[p][o] = val;
                }
            }
        }
        __syncthreads();

        {
            float s0[2] = {0.f, 0.f}, s1[2] = {0.f, 0.f};
#pragma unroll
            for (int k = 0; k < 3; k++) {
                const float* wrow = g_w2r + (size_t)k * HID * HID;
                for (int i = 0; i < HID; i += 2) {
                    float h0 = sh1[k][i], h1v = sh1[k][i + 1];
                    s0[0] = fmaf(wrow[(size_t)i * HID + tid], h0, s0[0]);
                    s0[1] = fmaf(wrow[(size_t)(i + 1) * HID + tid], h1v, s0[1]);
                    s1[0] = fmaf(wrow[(size_t)i * HID + tid + 256], h0, s1[0]);
                    s1[1] = fmaf(wrow[(size_t)(i + 1) * HID + tid + 256], h1v, s1[1]);
                }
            }
            sh2[tid]       = fmaxf(s0[0] + s0[1] + b2[tid], 0.f);
            sh2[tid + 256] = fmaxf(s1[0] + s1[1] + b2[tid + 256], 0.f);
        }
        __syncthreads();

        {
            float s0[2] = {0.f, 0.f}, s1[2] = {0.f, 0.f};
            for (int i = 0; i < HID; i += 2) {
                float h0 = sh2[i], h1v = sh2[i + 1];
                s0[0] = fmaf(g_wi1t[(size_t)i * HID + tid], h0, s0[0]);
                s0[1] = fmaf(g_wi1t[(size_t)(i + 1) * HID + tid], h1v, s0[1]);
                s1[0] = fmaf(g_wi1t[(size_t)i * HID + tid + 256], h0, s1[0]);
                s1[1] = fmaf(g_wi1t[(size_t)(i + 1) * HID + tid + 256], h1v, s1[1]);
            }
            float hh0 = fmaxf(s0[0] + s0[1] + bi1[tid], 0.f);
            float hh1 = fmaxf(s1[0] + s1[1] + bi1[tid + 256], 0.f);
            sred[tid] = hh0 * wi2[tid] + hh1 * wi2[tid + 256];
        }
        __syncthreads();

        for (int off = 128; off > 0; off >>= 1) {
            if (tid < off) sred[tid] += sred[tid + off];
            __syncthreads();
        }

        if (tid == 0) {
            float logit = sred[0] + bi2[0];
            float uu = u[idx];
            float g = -logf(-logf(uu + 1e-10f) + 1e-10f);
            float xx = logit + g;
            if (fabsf(xx) < 1e-3f) {
                unsigned pos = atomicAdd(&g_fix2_count, 1u);
                if (pos < FIXCAP) g_fix_list2[pos] = idx;
            } else {
                float soft = 1.0f / (1.0f + expf(-xx));
                float mk = (soft > 0.5f) ? 1.0f : 0.0f;
                apply_decision(idx, mk, v, out, out_size);
            }
        }
        __syncthreads();
    }
}

// ---------------- Tier-2 fixup: Kahan, exact ----------------
__global__ __launch_bounds__(256)
void fixup_kahan_kernel(const float* __restrict__ x, const float* __restrict__ v,
                        const float* __restrict__ u,
                        const float* __restrict__ b1, const float* __restrict__ b2,
                        const float* __restrict__ bi1, const float* __restrict__ bi2,
                        const float* __restrict__ wi2,
                        float* __restrict__ out, int out_size)
{
    __shared__ float sx[5][DMODEL];
    __shared__ float sh1[3][HID];
    __shared__ float sh2[HID];
    __shared__ float sred[HID];

    const int tid = threadIdx.x;
    unsigned cnt = g_fix2_count;
    int total = (cnt < FIXCAP) ? (int)cnt : FIXCAP;

    for (int item = blockIdx.x; item < total; item += gridDim.x) {
        int idx = g_fix_list2[item];
        int b = idx >> 13;
        int n = idx & (NSEQ - 1);

        for (int i = tid; i < 5 * DMODEL; i += 256) {
            int r = i >> 10, c = i & (DMODEL - 1);
            int pos = n - 2 + r;
            sx[r][c] = ((unsigned)pos < (unsigned)NSEQ)
                     ? x[((size_t)b * NSEQ + pos) * DMODEL + c] : 0.f;
        }
        __syncthreads();

        {
            float s[2][3], cp[2][3];
#pragma unroll
            for (int a = 0; a < 2; a++)
#pragma unroll
                for (int p = 0; p < 3; p++) { s[a][p] = 0.f; cp[a][p] = 0.f; }
#pragma unroll
            for (int k = 0; k < 3; k++) {
                const float* wrow = g_w1r + (size_t)k * DMODEL * HID;
                for (int i = 0; i < DMODEL; i++) {
                    float wa = wrow[(size_t)i * HID + tid];
                    float wb = wrow[(size_t)i * HID + tid + 256];
                    float x0 = sx[k + 0][i];
                    float x1 = sx[k + 1][i];
                    float x2 = sx[k + 2][i];
                    kadd(s[0][0], cp[0][0], wa * x0);
                    kadd(s[0][1], cp[0][1], wa * x1);
                    kadd(s[0][2], cp[0][2], wa * x2);
                    kadd(s[1][0], cp[1][0], wb * x0);
                    kadd(s[1][1], cp[1][1], wb * x1);
                    kadd(s[1][2], cp[1][2], wb * x2);
                }
            }
#pragma unroll
            for (int a = 0; a < 2; a++) {
                int o = tid + a * 256;
                float bo = b1[o];
#pragma unroll
                for (int p = 0; p < 3; p++) {
                    int pos = n - 1 + p;
                    float val = ((unsigned)pos < (unsigned)NSEQ)
                              ? fmaxf(s[a][p] + cp[a][p] + bo, 0.f) : 0.f;
                    sh1[p][o] = val;
                }
            }
        }
        __syncthreads();

        {
            float s0 = 0.f, c0 = 0.f, s1 = 0.f, c1 = 0.f;
#pragma unroll
            for (int k = 0; k < 3; k++) {
                const float* wrow = g_w2r + (size_t)k * HID * HID;
                for (int i = 0; i < HID; i++) {
                    float hv = sh1[k][i];
                    kadd(s0, c0, wrow[(size_t)i * HID + tid] * hv);
                    kadd(s1, c1, wrow[(size_t)i * HID + tid + 256] * hv);
                }
            }
            sh2[tid]       = fmaxf(s0 + c0 + b2[tid], 0.f);
            sh2[tid + 256] = fmaxf(s1 + c1 + b2[tid + 256], 0.f);
        }
        __syncthreads();

        {
            float s0 = 0.f, c0 = 0.f, s1 = 0.f, c1 = 0.f;
            for (int i = 0; i < HID; i++) {
                float hv = sh2[i];
                kadd(s0, c0, g_wi1t[(size_t)i * HID + tid] * hv);
                kadd(s1, c1, g_wi1t[(size_t)i * HID + tid + 256] * hv);
            }
            float hh0 = fmaxf(s0 + c0 + bi1[tid], 0.f);
            float hh1 = fmaxf(s1 + c1 + bi1[tid + 256], 0.f);
            sred[tid]       = hh0 * wi2[tid];
            sred[tid + 256] = hh1 * wi2[tid + 256];
        }
        __syncthreads();

        if (tid == 0) {
            float s = 0.f, cp = 0.f;
            for (int i = 0; i < HID; i++) kadd(s, cp, sred[i]);
            float logit = s + cp + bi2[0];
            float uu = u[idx];
            float g = -logf(-logf(uu + 1e-10f) + 1e-10f);
            float xx = logit + g;
            float soft = 1.0f / (1.0f + expf(-xx));
            float mk = (soft > 0.5f) ? 1.0f : 0.0f;
            apply_decision(idx, mk, v, out, out_size);
        }
        __syncthreads();
    }
}

// ---------------- tiny interp conv stack + final select ----------------
#define ITILE 128
__global__ __launch_bounds__(256)
void interp_kernel(const float* __restrict__ wi1, const float* __restrict__ bi1,
                   const float* __restrict__ wi2, const float* __restrict__ bi2,
                   const float* __restrict__ wi3, const float* __restrict__ bi3,
                   float* __restrict__ out, int out_size)
{
    __shared__ float sIn[2][ITILE + 12];
    __shared__ float sL1[32][ITILE + 8];
    __shared__ float sL2[32][ITILE + 4];

    const int b = blockIdx.x / (NSEQ / ITILE);
    const int t0 = (blockIdx.x % (NSEQ / ITILE)) * ITILE;
    const int tid = threadIdx.x;

    for (int i = tid; i < 2 * (ITILE + 12); i += 256) {
        int c = i / (ITILE + 12), p = i - c * (ITILE + 12);
        int q = t0 - 6 + p;
        float val = 0.f;
        if ((unsigned)q < (unsigned)NSEQ) val = g_sparse[((size_t)b * NSEQ + q) * 2 + c];
        sIn[c][p] = val;
    }
    __syncthreads();

    for (int i = tid; i < 32 * (ITILE + 8); i += 256) {
        int co = i / (ITILE + 8), p = i - co * (ITILE + 8);
        int apos = t0 - 4 + p;
        float val = 0.f;
        if ((unsigned)apos < (unsigned)NSEQ) {
            float s = bi1[co];
#pragma unroll
            for (int ci = 0; ci < 2; ci++)
#pragma unroll
                for (int k = 0; k < 5; k++)
                    s = fmaf(wi1[co * 10 + ci * 5 + k], sIn[ci][p + k], s);
            val = fmaxf(s, 0.f);
        }
        sL1[co][p] = val;
    }
    __syncthreads();

    for (int i = tid; i < 32 * (ITILE + 4); i += 256) {
        int co = i / (ITILE + 4), p = i - co * (ITILE + 4);
        int apos = t0 - 2 + p;
        float val = 0.f;
        if ((unsigned)apos < (unsigned)NSEQ) {
            float s = bi2[co];
            for (int ci = 0; ci < 32; ci++)
#pragma unroll
                for (int k = 0; k < 5; k++)
                    s = fmaf(wi2[co * 160 + ci * 5 + k], sL1[ci][p + k], s);
            val = fmaxf(s, 0.f);
        }
        sL2[co][p] = val;
    }
    __syncthreads();

    {
        int co = tid & 1, p = tid >> 1;
        float s = bi3[co];
        for (int ci = 0; ci < 32; ci++)
#pragma unroll
            for (int k = 0; k < 5; k++)
                s = fmaf(wi3[co * 160 + ci * 5 + k], sL2[ci][p + k], s);
        int gidx = b * NSEQ + t0 + p;
        float mk = g_mask[gidx];
        float sp = g_sparse[(size_t)gidx * 2 + co];
        out[(size_t)gidx * 2 + co] = (mk > 0.5f) ? sp : s;
    }

    if (blockIdx.x == 0 && tid == 0 && out_size >= 3 * MTOT + 1)
        out[3 * MTOT] = 1.0f - (float)g_mask_count / (float)MTOT;
}

// ---------------- launch ----------------
static void* symaddr(const void* sym) {
    void* p = nullptr;
    cudaGetSymbolAddress(&p, sym);
    return p;
}

extern "C" void kernel_launch(void* const* d_in, const int* in_sizes, int n_in,
                              void* d_out, int out_size)
{
    const float* x      = (const float*)d_in[0];
    const float* v      = (const float*)d_in[1];
    const float* u      = (const float*)d_in[2];
    const float* w_ctx1 = (const float*)d_in[3];
    const float* b_ctx1 = (const float*)d_in[4];
    const float* w_ctx2 = (const float*)d_in[5];
    const float* b_ctx2 = (const float*)d_in[6];
    const float* w_imp1 = (const float*)d_in[7];
    const float* b_imp1 = (const float*)d_in[8];
    const float* w_imp2 = (const float*)d_in[9];
    const float* b_imp2 = (const float*)d_in[10];
    const float* w_int1 = (const float*)d_in[11];
    const float* b_int1 = (const float*)d_in[12];
    const float* w_int2 = (const float*)d_in[13];
    const float* b_int2 = (const float*)d_in[14];
    const float* w_int3 = (const float*)d_in[15];
    const float* b_int3 = (const float*)d_in[16];
    float* out = (float*)d_out;

    __nv_bfloat16* w1th  = (__nv_bfloat16*)symaddr(g_w1th);
    __nv_bfloat16* w2th  = (__nv_bfloat16*)symaddr(g_w2th);
    __nv_bfloat16* wi1th = (__nv_bfloat16*)symaddr(g_wi1th);
    __nv_bfloat16* xph   = (__nv_bfloat16*)symaddr(g_xph);
    __nv_bfloat16* h1ph  = (__nv_bfloat16*)symaddr(g_h1ph);
    __nv_bfloat16* h2h   = (__nv_bfloat16*)symaddr(g_h2h);
    float* lpart = (float*)symaddr(g_logits_part);

    static bool attr_set = false;
    if (!attr_set) {
        cudaFuncSetAttribute(mma_gemm_kernel<DMODEL, 3, 0, true>,
                             cudaFuncAttributeMaxDynamicSharedMemorySize, MMA_SMEM);
        cudaFuncSetAttribute(mma_gemm_kernel<HID, 3, 1, true>,
                             cudaFuncAttributeMaxDynamicSharedMemorySize, MMA_SMEM);
        cudaFuncSetAttribute(mma_gemm_kernel<HID, 1, 2, false>,
                             cudaFuncAttributeMaxDynamicSharedMemorySize, MMA_SMEM);
        attr_set = true;
    }

    prep_kernel<<<128, 256>>>(w_ctx1, w_ctx2, w_imp1);
    pad_kernel<<<2048, 256>>>(x);

    const int gemmGrid = (MTOT / 128) * 4;
    mma_gemm_kernel<DMODEL, 3, 0, true><<<gemmGrid, 256, MMA_SMEM>>>(xph, w1th, b_ctx1, h1ph, nullptr);
    mma_gemm_kernel<HID, 3, 1, true><<<gemmGrid, 256, MMA_SMEM>>>(h1ph, w2th, b_ctx2, h2h, nullptr);
    mma_gemm_kernel<HID, 1, 2, false><<<gemmGrid, 256, MMA_SMEM>>>(h2h, wi1th, b_imp1, lpart, w_imp2);

    green_kernel<<<8, 256>>>(v);
    mask_kernel<<<MTOT / 256, 256>>>(u, v, b_imp2, out, out_size);
    fixup_fast_kernel<<<1024, 256>>>(x, v, u, b_ctx1, b_ctx2, b_imp1, b_imp2, w_imp2, out, out_size);
    fixup_kahan_kernel<<<64, 256>>>(x, v, u, b_ctx1, b_ctx2, b_imp1, b_imp2, w_imp2, out, out_size);
    interp_kernel<<<BATCH * (NSEQ / ITILE), 256>>>(w_int1, b_int1, w_int2, b_int2,
                                                   w_int3, b_int3, out, out_size);
}